// round 15
// baseline (speedup 1.0000x reference)
#include <cuda_runtime.h>
#include <math.h>

#define EPSV  1e-20f
#define L2EPS -66.438561897f
#define Hh 192
#define Ww 192
#define HW (Hh*Ww)
#define WSTR 37
#define WSLOT (32*WSTR)

__device__ float g_wcd[1024];     // channel_d [o][i]
__device__ float g_wsd[288];      // spatial_d [i][k]
__device__ float g_wce[1024];     // channel_e [o][i]
__device__ float g_wdir[512];     // [p][i][d]
__device__ float g_wse[1152];     // [i][d][k]
__device__ float g_wprop[128];    // [i][d]
__device__ float g_wpow0[128];    // [i][d]
__device__ float g_wpow1[128];    // [i][d]

__device__ __forceinline__ float sp_(float v){ return log1pf(expf(v)); }
__device__ __forceinline__ float sig_(float v){ return 1.f/(1.f+expf(-v)); }
__device__ __forceinline__ float ex2_(float v){
    float r; asm("ex2.approx.f32 %0, %1;" : "=f"(r) : "f"(v)); return r;
}
__device__ __forceinline__ float wsum_(float v){
#pragma unroll
    for(int m=16;m;m>>=1) v+=__shfl_xor_sync(0xffffffffu,v,m);
    return v;
}

// ---------------- prep: 5 blocks x 32 warps ----------------
__global__ void prep_kernel(const float* __restrict__ Wcd, const float* __restrict__ Wsd,
                            const float* __restrict__ Wce, const float* __restrict__ Wse0,
                            const float* __restrict__ Wse1, const float* __restrict__ Wse3,
                            const float* __restrict__ Wdir, const float* __restrict__ Wpow,
                            const float* __restrict__ Wprop)
{
    int blk=blockIdx.x;
    int t=threadIdx.x>>5, lane=threadIdx.x&31;
    if(blk==0){
        float v=sp_(Wcd[t*32+lane]);
        float s=wsum_(v);
        g_wcd[t*32+lane]=v/s;
    } else if(blk==1){
        float v=sp_(Wce[t*32+lane]);
        float s=wsum_(v);
        g_wce[t*32+lane]=v/s;
    } else if(blk==2){
        float v=0.f;
        if(lane<9) v=sp_(Wsd[t*6+(lane/3)*2+((lane%3)==1)]);
        float s=wsum_(v);
        if(lane<9) g_wsd[t*9+lane]=v/s;
        if(lane==0){
            float s0=sig_(Wprop[t*3+0]), s1=sig_(Wprop[t*3+1]), s2=sig_(Wprop[t*3+2]);
            g_wprop[t*4+0]=s1; g_wprop[t*4+1]=s0; g_wprop[t*4+2]=s1; g_wprop[t*4+3]=s2;
            float p0=sp_(Wpow[t*5+0]),p1=sp_(Wpow[t*5+1]),p2=sp_(Wpow[t*5+2]),
                  p3=sp_(Wpow[t*5+3]),p4=sp_(Wpow[t*5+4]);
            g_wpow0[t*4+0]=p0; g_wpow0[t*4+1]=p2; g_wpow0[t*4+2]=p1; g_wpow0[t*4+3]=p4;
            g_wpow1[t*4+0]=p1; g_wpow1[t*4+1]=p3; g_wpow1[t*4+2]=p0; g_wpow1[t*4+3]=p4;
        }
    } else if(blk==3){
        const int map[16]={0,1,2,3, 4,5,4,6, 2,1,0,3, 7,8,7,9};
        float v=0.f;
        if(lane<16) v=sp_(Wdir[t*10+map[lane]]);
        float s=v;
        s+=__shfl_xor_sync(0xffffffffu,s,1);
        s+=__shfl_xor_sync(0xffffffffu,s,2);
        if(lane<16) g_wdir[((lane>>2)*32+t)*4+(lane&3)]=v/s;
    } else {
        float v0=0.f,v1=0.f,v2=0.f,v3=0.f;
        if(lane<9){
            int h=lane/3,c=lane%3;
            v0=sp_(Wse0[t*9+lane]);
            v1=sp_(Wse1[t*6+h*2+(c==1)]);
            v2=sp_(Wse0[t*9+h*3+(2-c)]);
            v3=sp_(Wse3[t*6+h*2+(c==1)]);
        }
        float s0=wsum_(v0), s1=wsum_(v1), s2=wsum_(v2), s3=wsum_(v3);
        if(lane<9){
            g_wse[(t*4+0)*9+lane]=v0/s0;
            g_wse[(t*4+1)*9+lane]=v1/s1;
            g_wse[(t*4+2)*9+lane]=v2/s2;
            g_wse[(t*4+3)*9+lane]=v3/s3;
        }
    }
}

// dynamic smem (floats):
//  [0 .. 9472)    union: window ring (win_lv 4736 + win_cv 4736)  |  staging sh_ct (4224 float2 = 8448)
//  [9472 ..)      weights: wse 1152, wdir 512, wsd 288, prop 128, p0 128, p1 128,
//                 wceP 1024 (256 float4), wcdP 1024
#define K_SMEM (13856*4)

// ---------------- K2F3 fused, smem window ring, 3 CTAs/SM ----------------
__global__ void __launch_bounds__(256,3) k2f3(const float* __restrict__ x,
                                              const float* __restrict__ ece,
                                              const float* __restrict__ ce,
                                              float* __restrict__ dout)
{
    extern __shared__ float dsm[];
    float*  win_lv = dsm;                  // 4*WSLOT = 4736
    float*  win_cv = dsm+4736;             // 4736
    float2* sh_ct  = (float2*)dsm;         // 4224 float2, aliases window (used after it dies)
    float*  sh_wse = dsm+9472;
    float*  sh_wdir= sh_wse+1152;
    float*  sh_wsd = sh_wdir+512;
    float*  sh_wprop=sh_wsd+288;
    float*  sh_wp0 = sh_wprop+128;
    float*  sh_wp1 = sh_wp0+128;
    float4* sh_wceP=(float4*)(sh_wp1+128);
    float4* sh_wcdP=sh_wceP+256;

    int tid=threadIdx.x;
    for(int k=tid;k<1152;k+=256) sh_wse[k]=g_wse[k];
    for(int k=tid;k<512;k+=256)  sh_wdir[k]=g_wdir[k];
    {
        int ii=tid>>3, o4q=tid&7;
        sh_wceP[tid]=make_float4(g_wce[o4q*32+ii],g_wce[(o4q+8)*32+ii],
                                 g_wce[(o4q+16)*32+ii],g_wce[(o4q+24)*32+ii]);
        sh_wcdP[tid]=make_float4(g_wcd[o4q*32+ii],g_wcd[(o4q+8)*32+ii],
                                 g_wcd[(o4q+16)*32+ii],g_wcd[(o4q+24)*32+ii]);
    }
    for(int k=tid;k<288;k+=256) sh_wsd[k]=g_wsd[k];
    if(tid<128){ sh_wprop[tid]=g_wprop[tid]; sh_wp0[tid]=g_wpow0[tid]; sh_wp1[tid]=g_wpow1[tid]; }

    int t=blockIdx.x;
    int b=t/1152; int rem=t-b*1152;
    int y0=rem/6; int x0=(rem-y0*6)*32;
    int i=tid>>3, pq=tid&7;
    int xb=x0+pq*4;

    const float* dcd=x+(size_t)(b*32+i)*HW;
    const float* cdp=x+(size_t)(64+b*32+i)*HW;

    // fill one window row (36 cols per channel, cooperative) into ring slot
    auto FILL=[&](int yy,int slot){
        bool yok=((unsigned)yy<(unsigned)Hh);
        const float* rpd=dcd+yy*Ww;
        const float* rpc=cdp+yy*Ww;
        float4 xd=make_float4(0.f,0.f,0.f,0.f), xc=xd;
        if(yok){ xd=*reinterpret_cast<const float4*>(rpd+xb);
                 xc=*reinterpret_cast<const float4*>(rpc+xb); }
        float dvv[4]={xd.x,xd.y,xd.z,xd.w};
        float cww[4]={xc.x,xc.y,xc.z,xc.w};
        float* lvp=win_lv+slot*WSLOT+i*WSTR;
        float* cvp=win_cv+slot*WSLOT+i*WSTR;
#pragma unroll
        for(int k2=0;k2<4;k2++){
            float l=__log2f(dvv[k2])-__log2f(cww[k2]+EPSV);
            if(dvv[k2]<=0.f) l=-1e30f;
            lvp[2+pq*4+k2]=l;
            cvp[2+pq*4+k2]=cww[k2];
        }
        if(pq==0){
#pragma unroll
            for(int tq=0;tq<2;tq++){
                int col=x0-2+tq;
                bool ok=yok&&(col>=0);
                float dv=ok?rpd[col]:0.f, cw=ok?rpc[col]:0.f;
                float l=__log2f(dv)-__log2f(cw+EPSV);
                if(dv<=0.f) l=-1e30f;
                lvp[tq]=l; cvp[tq]=cw;
            }
        }
        if(pq==7){
#pragma unroll
            for(int tq=0;tq<2;tq++){
                int col=x0+32+tq;
                bool ok=yok&&(col<Ww);
                float dv=ok?rpd[col]:0.f, cw=ok?rpc[col]:0.f;
                float l=__log2f(dv)-__log2f(cw+EPSV);
                if(dv<=0.f) l=-1e30f;
                lvp[34+tq]=l; cvp[34+tq]=cw;
            }
        }
    };

    __syncthreads();   // weights ready (also covers initial use)

    // prologue: fill 4 ring slots with rows y0-2 .. y0+1
    FILL(y0-2,0); FILL(y0-1,1); FILL(y0,2); FILL(y0+1,3);
    __syncthreads();

    float s_c[4][4], s_e[4][4];
#pragma unroll
    for(int d=0;d<4;d++)
#pragma unroll
        for(int j=0;j<4;j++){ s_c[d][j]=0.f; s_e[d][j]=0.f; }

    const int dA[4]={0,1,2,2};
    const int dB[4]={2,1,0,0};

#pragma unroll
    for(int ry=0;ry<3;ry++){
        int yy=y0-1+ry;
        bool row_ok=((unsigned)yy<(unsigned)Hh);
        // window base pointers (slot = (ry+m)&3 for row yy-1+m), offset by pq*4
        const float* lvm1=win_lv+((ry  )&3)*WSLOT+i*WSTR+pq*4;
        const float* cvm1=win_cv+((ry  )&3)*WSLOT+i*WSTR+pq*4;
        const float* lv0 =win_lv+((ry+1)&3)*WSLOT+i*WSTR+pq*4;
        const float* cv0 =win_cv+((ry+1)&3)*WSLOT+i*WSTR+pq*4;
        const float* lvp1=win_lv+((ry+2)&3)*WSLOT+i*WSTR+pq*4;
        const float* cvp1=win_cv+((ry+2)&3)*WSLOT+i*WSTR+pq*4;
        if(row_ok){
#pragma unroll
            for(int d=0;d<4;d++){
                size_t poff=(size_t)((b*32+i)*4+d)*HW + (size_t)yy*Ww;
                float4 ce4=*reinterpret_cast<const float4*>(ce+poff+xb);
                float4 ec4=*reinterpret_cast<const float4*>(ece+poff+xb);
                float cem1=__shfl_up_sync(0xffffffffu,ce4.w,1);
                float ecm1=__shfl_up_sync(0xffffffffu,ec4.w,1);
                float cep4=__shfl_down_sync(0xffffffffu,ce4.x,1);
                float ecp4=__shfl_down_sync(0xffffffffu,ec4.x,1);
                if(pq==0){
                    cem1=(xb>=1)? ce[poff+xb-1]:0.f;
                    ecm1=(xb>=1)? ece[poff+xb-1]:0.f;
                }
                if(pq==7){
                    cep4=((xb+4)<Ww)? ce[poff+xb+4]:0.f;
                    ecp4=((xb+4)<Ww)? ece[poff+xb+4]:0.f;
                }
                float cevv[6]={cem1,ce4.x,ce4.y,ce4.z,ce4.w,cep4};
                float ecvv[6]={ecm1,ec4.x,ec4.y,ec4.z,ec4.w,ecp4};
                float wp=sh_wprop[i*4+d], p0=sh_wp0[i*4+d], p1=sh_wp1[i*4+d];
                const float* LA=(d<3)? lvm1 : lv0;
                const float* CA=(d<3)? cvm1 : cv0;
                const float* LB=(d<3)? lvp1 : lv0;
                const float* CB=(d<3)? cvp1 : cv0;
                float cein[6],ecein[6];
#pragma unroll
                for(int k=0;k<6;k++){
                    int q=xb-1+k;
                    bool vq=((unsigned)q<(unsigned)Ww);
                    float lA=LA[k+dA[d]], lB=LB[k+dB[d]];
                    float la=fminf(fmaxf(lA-fmaxf(lB,L2EPS),L2EPS),0.f);
                    float lb=fminf(fmaxf(lB-fmaxf(lA,L2EPS),L2EPS),0.f);
                    float en=ex2_(fminf(p0*la,p1*lb));
                    float cn=CA[k+dA[d]]*CB[k+dB[d]];
                    cein[k] =vq? (cevv[k]*wp+cn*(1.f-wp))    : 0.f;
                    ecein[k]=vq? (ecvv[k]*wp+en*cn*(1.f-wp)) : 0.f;
                }
                const float* w=sh_wse+(i*4+d)*9;
                float w0=w[ry*3],w1=w[ry*3+1],w2=w[ry*3+2];
#pragma unroll
                for(int j=0;j<4;j++){
                    s_c[d][j]+=w0*cein[j]+w1*cein[j+1]+w2*cein[j+2];
                    s_e[d][j]+=w0*ecein[j]+w1*ecein[j+1]+w2*ecein[j+2];
                }
            }
        }
        if(ry==0){
            __syncthreads();        // slot0 (row y0-2) readers done
            FILL(y0+2,0);           // refill; ry1 uses slots 1,2,3 (disjoint)
        }
        if(ry==1) __syncthreads();  // fill(slot0) visible before ry2
    }
    __syncthreads();                // window dead; staging may alias it

    // dir mix -> packed staging (STS.64, conflict-free)
#pragma unroll
    for(int p=0;p<4;p++){
        float wd0=sh_wdir[(p*32+i)*4+0];
        float wd1=sh_wdir[(p*32+i)*4+1];
        float wd2=sh_wdir[(p*32+i)*4+2];
        float wd3=sh_wdir[(p*32+i)*4+3];
#pragma unroll
        for(int j=0;j<4;j++){
            float tc=wd0*s_c[0][j]+wd1*s_c[1][j]+wd2*s_c[2][j]+wd3*s_c[3][j];
            float te=wd0*s_e[0][j]+wd1*s_e[1][j]+wd2*s_e[2][j]+wd3*s_e[3][j];
            sh_ct[p*1056+(pq*4+j)*33+i]=make_float2(tc,te);
        }
    }
    __syncthreads();

    // ---- phase B: channel mix; warp = o4, 32 px; 4 o's via packed weights ----
    int o4=tid>>5, px=tid&31;
    float e[4][5];
    {
        float accc[4][4], acce[4][4];
#pragma unroll
        for(int og=0;og<4;og++)
#pragma unroll
            for(int p=0;p<4;p++){ accc[og][p]=0.f; acce[og][p]=0.f; }
#pragma unroll 4
        for(int ii=0;ii<32;ii++){
            float4 wv=sh_wceP[ii*8+o4];
#pragma unroll
            for(int p=0;p<4;p++){
                float2 tv=sh_ct[p*1056+px*33+ii];
                accc[0][p]+=wv.x*tv.x; acce[0][p]+=wv.x*tv.y;
                accc[1][p]+=wv.y*tv.x; acce[1][p]+=wv.y*tv.y;
                accc[2][p]+=wv.z*tv.x; acce[2][p]+=wv.z*tv.y;
                accc[3][p]+=wv.w*tv.x; acce[3][p]+=wv.w*tv.y;
            }
        }
        const size_t ece_off=(size_t)128*HW;
        const size_t ceo_off=(size_t)384*HW;
#pragma unroll
        for(int og=0;og<4;og++){
            int o=o4+og*8;
            size_t base=(size_t)((b*32+o)*4)*HW + (size_t)y0*Ww + x0 + px;
#pragma unroll
            for(int p=0;p<4;p++){
                dout[ece_off+base+(size_t)p*HW]=acce[og][p];
                dout[ceo_off+base+(size_t)p*HW]=accc[og][p];
                e[og][p]=fminf(fmaxf(__fdividef(acce[og][p],accc[og][p]+EPSV),EPSV),1.f);
            }
            e[og][4]=1.f;
        }
    }
    __syncthreads();   // all phase-B reads of sh_ct done before reuse

    // ---- phase C: e9-modulated depthwise of dcd/cd (channel o, 1 px each) ----
    const int emap[9]={0,1,2,3,4,3,2,1,0};
#pragma unroll
    for(int og=0;og<4;og++){
        int o=o4+og*8;
        const float* dcd2=x+(size_t)(b*32+o)*HW;
        const float* cdp2=x+(size_t)(64+b*32+o)*HW;
        const float* w=sh_wsd+o*9;
        float md=0.f, mc=0.f;
#pragma unroll
        for(int ry=0;ry<3;ry++){
            int yy=y0-1+ry;
            bool yok=((unsigned)yy<(unsigned)Hh);
            float dv=0.f, cvv=0.f;
            if(yok){
                dv =dcd2[yy*Ww+x0+px];
                cvv=cdp2[yy*Ww+x0+px];
            }
            float lfd=__shfl_up_sync(0xffffffffu,dv,1);
            float lfc=__shfl_up_sync(0xffffffffu,cvv,1);
            float rtd=__shfl_down_sync(0xffffffffu,dv,1);
            float rtc=__shfl_down_sync(0xffffffffu,cvv,1);
            if(px==0){
                lfd=(yok&&x0>0)? dcd2[yy*Ww+x0-1]:0.f;
                lfc=(yok&&x0>0)? cdp2[yy*Ww+x0-1]:0.f;
            }
            if(px==31){
                rtd=(yok&&(x0+32)<Ww)? dcd2[yy*Ww+x0+32]:0.f;
                rtc=(yok&&(x0+32)<Ww)? cdp2[yy*Ww+x0+32]:0.f;
            }
            float rd[3]={lfd,dv,rtd};
            float rc[3]={lfc,cvv,rtc};
#pragma unroll
            for(int rx=0;rx<3;rx++){
                int k=ry*3+rx;
                float f=w[k]*e[og][emap[k]];
                md+=f*rd[rx];
                mc+=f*rc[rx];
            }
        }
        sh_ct[px*33+o]=make_float2(md,mc);
    }
    __syncthreads();

    // ---- phase D: 32x32 mix -> main outputs ----
    float ad2[4]={0.f,0.f,0.f,0.f}, ac2[4]={0.f,0.f,0.f,0.f};
#pragma unroll 4
    for(int ii=0;ii<32;ii++){
        float4 wv=sh_wcdP[ii*8+o4];
        float2 v=sh_ct[px*33+ii];
        ad2[0]+=wv.x*v.x; ac2[0]+=wv.x*v.y;
        ad2[1]+=wv.y*v.x; ac2[1]+=wv.y*v.y;
        ad2[2]+=wv.z*v.x; ac2[2]+=wv.z*v.y;
        ad2[3]+=wv.w*v.x; ac2[3]+=wv.w*v.y;
    }
#pragma unroll
    for(int og=0;og<4;og++){
        int o=o4+og*8;
        dout[(size_t)(b*32+o)*HW+(size_t)y0*Ww+x0+px]   =ad2[og];
        dout[(size_t)(64+b*32+o)*HW+(size_t)y0*Ww+x0+px]=ac2[og];
    }
}

extern "C" void kernel_launch(void* const* d_in, const int* in_sizes, int n_in,
                              void* d_out, int out_size)
{
    const float* x   =(const float*)d_in[0];
    const float* ece =(const float*)d_in[1];
    const float* ce  =(const float*)d_in[2];
    static bool attr_done=false;
    if(!attr_done){
        cudaFuncSetAttribute(k2f3, cudaFuncAttributeMaxDynamicSharedMemorySize, K_SMEM);
        attr_done=true;
    }
    prep_kernel<<<5,1024>>>((const float*)d_in[3],(const float*)d_in[4],
                            (const float*)d_in[5],(const float*)d_in[6],
                            (const float*)d_in[7],(const float*)d_in[8],
                            (const float*)d_in[9],(const float*)d_in[10],
                            (const float*)d_in[11]);
    k2f3<<<2304,256,K_SMEM>>>(x,ece,ce,(float*)d_out);
}

// round 16
// speedup vs baseline: 1.1066x; 1.1066x over previous
#include <cuda_runtime.h>
#include <math.h>

#define EPSV  1e-20f
#define L2EPS -66.438561897f
#define Hh 192
#define Ww 192
#define HW (Hh*Ww)

__device__ float g_wcd[1024];     // channel_d [o][i]
__device__ float g_wsd[288];      // spatial_d [i][k]
__device__ float g_wce[1024];     // channel_e [o][i]
__device__ float g_wdir[512];     // [p][i][d]
__device__ float g_wse[1152];     // [i][d][k]
__device__ float g_wprop[128];    // [i][d]
__device__ float g_wpow0[128];    // [i][d]
__device__ float g_wpow1[128];    // [i][d]

__device__ __forceinline__ float sp_(float v){ return log1pf(expf(v)); }
__device__ __forceinline__ float sig_(float v){ return 1.f/(1.f+expf(-v)); }
__device__ __forceinline__ float ex2_(float v){
    float r; asm("ex2.approx.f32 %0, %1;" : "=f"(r) : "f"(v)); return r;
}
__device__ __forceinline__ float wsum_(float v){
#pragma unroll
    for(int m=16;m;m>>=1) v+=__shfl_xor_sync(0xffffffffu,v,m);
    return v;
}

// ---------------- prep: 5 blocks x 32 warps ----------------
__global__ void prep_kernel(const float* __restrict__ Wcd, const float* __restrict__ Wsd,
                            const float* __restrict__ Wce, const float* __restrict__ Wse0,
                            const float* __restrict__ Wse1, const float* __restrict__ Wse3,
                            const float* __restrict__ Wdir, const float* __restrict__ Wpow,
                            const float* __restrict__ Wprop)
{
    int blk=blockIdx.x;
    int t=threadIdx.x>>5, lane=threadIdx.x&31;
    if(blk==0){
        float v=sp_(Wcd[t*32+lane]);
        float s=wsum_(v);
        g_wcd[t*32+lane]=v/s;
    } else if(blk==1){
        float v=sp_(Wce[t*32+lane]);
        float s=wsum_(v);
        g_wce[t*32+lane]=v/s;
    } else if(blk==2){
        float v=0.f;
        if(lane<9) v=sp_(Wsd[t*6+(lane/3)*2+((lane%3)==1)]);
        float s=wsum_(v);
        if(lane<9) g_wsd[t*9+lane]=v/s;
        if(lane==0){
            float s0=sig_(Wprop[t*3+0]), s1=sig_(Wprop[t*3+1]), s2=sig_(Wprop[t*3+2]);
            g_wprop[t*4+0]=s1; g_wprop[t*4+1]=s0; g_wprop[t*4+2]=s1; g_wprop[t*4+3]=s2;
            float p0=sp_(Wpow[t*5+0]),p1=sp_(Wpow[t*5+1]),p2=sp_(Wpow[t*5+2]),
                  p3=sp_(Wpow[t*5+3]),p4=sp_(Wpow[t*5+4]);
            g_wpow0[t*4+0]=p0; g_wpow0[t*4+1]=p2; g_wpow0[t*4+2]=p1; g_wpow0[t*4+3]=p4;
            g_wpow1[t*4+0]=p1; g_wpow1[t*4+1]=p3; g_wpow1[t*4+2]=p0; g_wpow1[t*4+3]=p4;
        }
    } else if(blk==3){
        const int map[16]={0,1,2,3, 4,5,4,6, 2,1,0,3, 7,8,7,9};
        float v=0.f;
        if(lane<16) v=sp_(Wdir[t*10+map[lane]]);
        float s=v;
        s+=__shfl_xor_sync(0xffffffffu,s,1);
        s+=__shfl_xor_sync(0xffffffffu,s,2);
        if(lane<16) g_wdir[((lane>>2)*32+t)*4+(lane&3)]=v/s;
    } else {
        float v0=0.f,v1=0.f,v2=0.f,v3=0.f;
        if(lane<9){
            int h=lane/3,c=lane%3;
            v0=sp_(Wse0[t*9+lane]);
            v1=sp_(Wse1[t*6+h*2+(c==1)]);
            v2=sp_(Wse0[t*9+h*3+(2-c)]);
            v3=sp_(Wse3[t*6+h*2+(c==1)]);
        }
        float s0=wsum_(v0), s1=wsum_(v1), s2=wsum_(v2), s3=wsum_(v3);
        if(lane<9){
            g_wse[(t*4+0)*9+lane]=v0/s0;
            g_wse[(t*4+1)*9+lane]=v1/s1;
            g_wse[(t*4+2)*9+lane]=v2/s2;
            g_wse[(t*4+3)*9+lane]=v3/s3;
        }
    }
}

// Load one x-row window (8 cols xb-2..xb+5) of (log-ratio, cd) into LV/CV.
// No dv>0 select: __log2f(0) = -inf is the natural sentinel.
#define LOAD_ROW(yy, LV, CV) do{                                              \
    int yy_=(yy);                                                             \
    bool yok_=((unsigned)yy_<(unsigned)Hh);                                   \
    const float* rpd_=dcd+yy_*Ww;                                             \
    const float* rpc_=cdp+yy_*Ww;                                             \
    float4 xd_=make_float4(0.f,0.f,0.f,0.f), xc_=xd_;                         \
    if(yok_){ xd_=*reinterpret_cast<const float4*>(rpd_+xb);                  \
              xc_=*reinterpret_cast<const float4*>(rpc_+xb); }                \
    float dm2_=__shfl_up_sync(0xffffffffu,xd_.z,1);                           \
    float dm1_=__shfl_up_sync(0xffffffffu,xd_.w,1);                           \
    float cm2_=__shfl_up_sync(0xffffffffu,xc_.z,1);                           \
    float cm1_=__shfl_up_sync(0xffffffffu,xc_.w,1);                           \
    float dp4_=__shfl_down_sync(0xffffffffu,xd_.x,1);                         \
    float dp5_=__shfl_down_sync(0xffffffffu,xd_.y,1);                         \
    float cp4_=__shfl_down_sync(0xffffffffu,xc_.x,1);                         \
    float cp5_=__shfl_down_sync(0xffffffffu,xc_.y,1);                         \
    if(pq==0){                                                                \
        dm2_=(yok_&&xb>=2)? rpd_[xb-2]:0.f;                                   \
        dm1_=(yok_&&xb>=1)? rpd_[xb-1]:0.f;                                   \
        cm2_=(yok_&&xb>=2)? rpc_[xb-2]:0.f;                                   \
        cm1_=(yok_&&xb>=1)? rpc_[xb-1]:0.f;                                   \
    }                                                                         \
    if(pq==7){                                                                \
        dp4_=(yok_&&(xb+4)<Ww)? rpd_[xb+4]:0.f;                               \
        dp5_=(yok_&&(xb+5)<Ww)? rpd_[xb+5]:0.f;                               \
        cp4_=(yok_&&(xb+4)<Ww)? rpc_[xb+4]:0.f;                               \
        cp5_=(yok_&&(xb+5)<Ww)? rpc_[xb+5]:0.f;                               \
    }                                                                         \
    float dv_[8]={dm2_,dm1_,xd_.x,xd_.y,xd_.z,xd_.w,dp4_,dp5_};               \
    float cw_[8]={cm2_,cm1_,xc_.x,xc_.y,xc_.z,xc_.w,cp4_,cp5_};               \
    _Pragma("unroll")                                                         \
    for(int m_=0;m_<8;m_++){                                                  \
        CV[m_]=cw_[m_];                                                       \
        LV[m_]=__log2f(dv_[m_])-__log2f(cw_[m_]+EPSV);                        \
    }                                                                         \
}while(0)

// ---------------- K2F3 fully fused (R14 base + collapsed clamp chain) ----------------
__global__ void __launch_bounds__(256,2) k2f3(const float* __restrict__ x,
                                              const float* __restrict__ ece,
                                              const float* __restrict__ ce,
                                              float* __restrict__ dout)
{
    __shared__ float2 sh_ct[4224];     // packed (ce_t, ece_t): [p][px*33+i]; later (md,mc)
    __shared__ float sh_wse[1152];
    __shared__ float sh_wdir[512];
    __shared__ float4 sh_wceP[256];    // [ii*8+o4]
    __shared__ float4 sh_wcdP[256];    // [ii*8+o4]
    __shared__ float sh_wsd[288];
    __shared__ float sh_wprop[128], sh_wp0[128], sh_wp1[128];
    int tid=threadIdx.x;
    for(int k=tid;k<1152;k+=256) sh_wse[k]=g_wse[k];
    for(int k=tid;k<512;k+=256)  sh_wdir[k]=g_wdir[k];
    {
        int ii=tid>>3, o4q=tid&7;
        sh_wceP[tid]=make_float4(g_wce[o4q*32+ii],g_wce[(o4q+8)*32+ii],
                                 g_wce[(o4q+16)*32+ii],g_wce[(o4q+24)*32+ii]);
        sh_wcdP[tid]=make_float4(g_wcd[o4q*32+ii],g_wcd[(o4q+8)*32+ii],
                                 g_wcd[(o4q+16)*32+ii],g_wcd[(o4q+24)*32+ii]);
    }
    for(int k=tid;k<288;k+=256) sh_wsd[k]=g_wsd[k];
    if(tid<128){ sh_wprop[tid]=g_wprop[tid]; sh_wp0[tid]=g_wpow0[tid]; sh_wp1[tid]=g_wpow1[tid]; }

    int t=blockIdx.x;
    int b=t/1152; int rem=t-b*1152;
    int y0=rem/6; int x0=(rem-y0*6)*32;
    int i=tid>>3, pq=tid&7;
    int xb=x0+pq*4;
    __syncthreads();

    {   // ---- phase A: k1 on the fly + depthwise (channel i, 4 px) ----
        const float* dcd=x+(size_t)(b*32+i)*HW;
        const float* cdp=x+(size_t)(64+b*32+i)*HW;

        float lv0[8],lv1[8],lv2[8],cv0[8],cv1[8],cv2[8];
        LOAD_ROW(y0-2,lv0,cv0);
        LOAD_ROW(y0-1,lv1,cv1);
        LOAD_ROW(y0  ,lv2,cv2);

        float s_c[4][4], s_e[4][4];
#pragma unroll
        for(int d=0;d<4;d++)
#pragma unroll
            for(int j=0;j<4;j++){ s_c[d][j]=0.f; s_e[d][j]=0.f; }

        const int dA[4]={0,1,2,2};
        const int dB[4]={2,1,0,0};

#pragma unroll
        for(int ry=0;ry<3;ry++){
            int yy=y0-1+ry;
            bool row_ok=((unsigned)yy<(unsigned)Hh);
            const float* LVm1 = (ry==0)? lv0 : (ry==1)? lv1 : lv2;
            const float* CVm1 = (ry==0)? cv0 : (ry==1)? cv1 : cv2;
            const float* LV0  = (ry==0)? lv1 : (ry==1)? lv2 : lv0;
            const float* CV0  = (ry==0)? cv1 : (ry==1)? cv2 : cv0;
            const float* LVp1 = (ry==0)? lv2 : (ry==1)? lv0 : lv1;
            const float* CVp1 = (ry==0)? cv2 : (ry==1)? cv0 : cv1;
            if(row_ok){
#pragma unroll
                for(int d=0;d<4;d++){
                    size_t poff=(size_t)((b*32+i)*4+d)*HW + (size_t)yy*Ww;
                    float4 ce4=*reinterpret_cast<const float4*>(ce+poff+xb);
                    float4 ec4=*reinterpret_cast<const float4*>(ece+poff+xb);
                    float cem1=__shfl_up_sync(0xffffffffu,ce4.w,1);
                    float ecm1=__shfl_up_sync(0xffffffffu,ec4.w,1);
                    float cep4=__shfl_down_sync(0xffffffffu,ce4.x,1);
                    float ecp4=__shfl_down_sync(0xffffffffu,ec4.x,1);
                    if(pq==0){
                        cem1=(xb>=1)? ce[poff+xb-1]:0.f;
                        ecm1=(xb>=1)? ece[poff+xb-1]:0.f;
                    }
                    if(pq==7){
                        cep4=((xb+4)<Ww)? ce[poff+xb+4]:0.f;
                        ecp4=((xb+4)<Ww)? ece[poff+xb+4]:0.f;
                    }
                    float cevv[6]={cem1,ce4.x,ce4.y,ce4.z,ce4.w,cep4};
                    float ecvv[6]={ecm1,ec4.x,ec4.y,ec4.z,ec4.w,ecp4};
                    float wp=sh_wprop[i*4+d], p0=sh_wp0[i*4+d], p1=sh_wp1[i*4+d];
                    const float* LA=(d<3)? LVm1 : LV0;
                    const float* CA=(d<3)? CVm1 : CV0;
                    const float* LB=(d<3)? LVp1 : LV0;
                    const float* CB=(d<3)? CVp1 : CV0;
                    float cein[6],ecein[6];
#pragma unroll
                    for(int k=0;k<6;k++){
                        int q=xb-1+k;
                        bool vq=((unsigned)q<(unsigned)Ww);
                        float dd=LA[k+dA[d]]-LB[k+dB[d]];
                        float t0=p0*fmaxf(dd,L2EPS);
                        float t1=p1*fmaxf(-dd,L2EPS);
                        float en=ex2_(fminf(t0,t1));
                        float cn=CA[k+dA[d]]*CB[k+dB[d]];
                        cein[k] =vq? (cevv[k]*wp+cn*(1.f-wp))    : 0.f;
                        ecein[k]=vq? (ecvv[k]*wp+en*cn*(1.f-wp)) : 0.f;
                    }
                    const float* w=sh_wse+(i*4+d)*9;
                    float w0=w[ry*3],w1=w[ry*3+1],w2=w[ry*3+2];
#pragma unroll
                    for(int j=0;j<4;j++){
                        s_c[d][j]+=w0*cein[j]+w1*cein[j+1]+w2*cein[j+2];
                        s_e[d][j]+=w0*ecein[j]+w1*ecein[j+1]+w2*ecein[j+2];
                    }
                }
            }
            if(ry==0) LOAD_ROW(y0+1,lv0,cv0);
            if(ry==1) LOAD_ROW(y0+2,lv1,cv1);
        }

        // dir mix -> packed staging (STS.64, conflict-free)
#pragma unroll
        for(int p=0;p<4;p++){
            float wd0=sh_wdir[(p*32+i)*4+0];
            float wd1=sh_wdir[(p*32+i)*4+1];
            float wd2=sh_wdir[(p*32+i)*4+2];
            float wd3=sh_wdir[(p*32+i)*4+3];
#pragma unroll
            for(int j=0;j<4;j++){
                float tc=wd0*s_c[0][j]+wd1*s_c[1][j]+wd2*s_c[2][j]+wd3*s_c[3][j];
                float te=wd0*s_e[0][j]+wd1*s_e[1][j]+wd2*s_e[2][j]+wd3*s_e[3][j];
                sh_ct[p*1056+(pq*4+j)*33+i]=make_float2(tc,te);
            }
        }
    }
    __syncthreads();

    // ---- phase B: channel mix; warp = o4, 32 px; 4 o's via packed weights ----
    int o4=tid>>5, px=tid&31;
    float e[4][5];
    {
        float accc[4][4], acce[4][4];
#pragma unroll
        for(int og=0;og<4;og++)
#pragma unroll
            for(int p=0;p<4;p++){ accc[og][p]=0.f; acce[og][p]=0.f; }
#pragma unroll 4
        for(int ii=0;ii<32;ii++){
            float4 wv=sh_wceP[ii*8+o4];
#pragma unroll
            for(int p=0;p<4;p++){
                float2 tv=sh_ct[p*1056+px*33+ii];
                accc[0][p]+=wv.x*tv.x; acce[0][p]+=wv.x*tv.y;
                accc[1][p]+=wv.y*tv.x; acce[1][p]+=wv.y*tv.y;
                accc[2][p]+=wv.z*tv.x; acce[2][p]+=wv.z*tv.y;
                accc[3][p]+=wv.w*tv.x; acce[3][p]+=wv.w*tv.y;
            }
        }
        const size_t ece_off=(size_t)128*HW;
        const size_t ceo_off=(size_t)384*HW;
#pragma unroll
        for(int og=0;og<4;og++){
            int o=o4+og*8;
            size_t base=(size_t)((b*32+o)*4)*HW + (size_t)y0*Ww + x0 + px;
#pragma unroll
            for(int p=0;p<4;p++){
                dout[ece_off+base+(size_t)p*HW]=acce[og][p];
                dout[ceo_off+base+(size_t)p*HW]=accc[og][p];
                e[og][p]=fminf(fmaxf(__fdividef(acce[og][p],accc[og][p]+EPSV),EPSV),1.f);
            }
            e[og][4]=1.f;
        }
    }
    __syncthreads();   // all phase-B reads of sh_ct done before reuse

    // ---- phase C: e9-modulated depthwise of dcd/cd (channel o, 1 px each) ----
    const int emap[9]={0,1,2,3,4,3,2,1,0};
#pragma unroll
    for(int og=0;og<4;og++){
        int o=o4+og*8;
        const float* dcd2=x+(size_t)(b*32+o)*HW;
        const float* cdp2=x+(size_t)(64+b*32+o)*HW;
        const float* w=sh_wsd+o*9;
        float md=0.f, mc=0.f;
#pragma unroll
        for(int ry=0;ry<3;ry++){
            int yy=y0-1+ry;
            bool yok=((unsigned)yy<(unsigned)Hh);
            float dv=0.f, cvv=0.f;
            if(yok){
                dv =dcd2[yy*Ww+x0+px];
                cvv=cdp2[yy*Ww+x0+px];
            }
            float lfd=__shfl_up_sync(0xffffffffu,dv,1);
            float lfc=__shfl_up_sync(0xffffffffu,cvv,1);
            float rtd=__shfl_down_sync(0xffffffffu,dv,1);
            float rtc=__shfl_down_sync(0xffffffffu,cvv,1);
            if(px==0){
                lfd=(yok&&x0>0)? dcd2[yy*Ww+x0-1]:0.f;
                lfc=(yok&&x0>0)? cdp2[yy*Ww+x0-1]:0.f;
            }
            if(px==31){
                rtd=(yok&&(x0+32)<Ww)? dcd2[yy*Ww+x0+32]:0.f;
                rtc=(yok&&(x0+32)<Ww)? cdp2[yy*Ww+x0+32]:0.f;
            }
            float rd[3]={lfd,dv,rtd};
            float rc[3]={lfc,cvv,rtc};
#pragma unroll
            for(int rx=0;rx<3;rx++){
                int k=ry*3+rx;
                float f=w[k]*e[og][emap[k]];
                md+=f*rd[rx];
                mc+=f*rc[rx];
            }
        }
        sh_ct[px*33+o]=make_float2(md,mc);
    }
    __syncthreads();

    // ---- phase D: 32x32 mix -> main outputs ----
    float ad2[4]={0.f,0.f,0.f,0.f}, ac2[4]={0.f,0.f,0.f,0.f};
#pragma unroll 4
    for(int ii=0;ii<32;ii++){
        float4 wv=sh_wcdP[ii*8+o4];
        float2 v=sh_ct[px*33+ii];
        ad2[0]+=wv.x*v.x; ac2[0]+=wv.x*v.y;
        ad2[1]+=wv.y*v.x; ac2[1]+=wv.y*v.y;
        ad2[2]+=wv.z*v.x; ac2[2]+=wv.z*v.y;
        ad2[3]+=wv.w*v.x; ac2[3]+=wv.w*v.y;
    }
#pragma unroll
    for(int og=0;og<4;og++){
        int o=o4+og*8;
        dout[(size_t)(b*32+o)*HW+(size_t)y0*Ww+x0+px]   =ad2[og];
        dout[(size_t)(64+b*32+o)*HW+(size_t)y0*Ww+x0+px]=ac2[og];
    }
}

extern "C" void kernel_launch(void* const* d_in, const int* in_sizes, int n_in,
                              void* d_out, int out_size)
{
    const float* x   =(const float*)d_in[0];
    const float* ece =(const float*)d_in[1];
    const float* ce  =(const float*)d_in[2];
    prep_kernel<<<5,1024>>>((const float*)d_in[3],(const float*)d_in[4],
                            (const float*)d_in[5],(const float*)d_in[6],
                            (const float*)d_in[7],(const float*)d_in[8],
                            (const float*)d_in[9],(const float*)d_in[10],
                            (const float*)d_in[11]);
    k2f3<<<2304,256>>>(x,ece,ce,(float*)d_out);
}